// round 8
// baseline (speedup 1.0000x reference)
#include <cuda_runtime.h>
#include <cuda_bf16.h>
#include <math.h>
#include <stdint.h>

// ---------------- problem constants ----------------
#define B_  8
#define T_  4096
#define D_  256
#define M_  (B_ * T_)      // 32768
#define K_  256
#define N_TOT 512

// ---------------- scan chunking ----------------
#define LCH 64
#define NCH (T_ / LCH)          // 64 chunks per batch
#define NBLK ((M_ / LCH) * 2)   // 1024 fused blocks

// ---------------- scratch (static device allocations) ----------------
__device__ uint4 g_Whi4[(N_TOT * K_) / 8];   // permuted rows (see wsplit)
__device__ uint4 g_Wlo4[(N_TOT * K_) / 8];
__device__ uint4 g_Ahi4[((size_t)M_ * K_) / 8];  // [m][k] bf16 hi
__device__ uint4 g_Alo4[((size_t)M_ * K_) / 8];  // [m][k] bf16 lo
// decoupled-lookback state
__device__ float    g_SA [NBLK * 128];
__device__ float    g_SHl[NBLK * 128];
__device__ float    g_SHI[NBLK * 128];
__device__ uint32_t g_flag[NBLK * 128];

// ---------------- smem layout ----------------
#define SM_AHI   0          // A_hi [64][256] bf16 swizzled, 32KB
#define SM_ALO   32768
#define SM_W0    65536      // W buffer0: hi 32KB + lo 32KB
#define SM_W1    131072
#define SM_WLOFF 32768
#define SM_BIAS  196608
#define SM_MK    197632
#define SM_TOTAL 197888
#define SM_XS    0          // epilogue staging (reuses A/W space)
#define SM_FS    36864
#define STG      136

// ---------------- asm helpers (base sm_103 features only) ----------------
__device__ __forceinline__ uint32_t smem_u32(const void* p) {
    uint32_t a;
    asm("{ .reg .u64 t; cvta.to.shared.u64 t, %1; cvt.u32.u64 %0, t; }" : "=r"(a) : "l"(p));
    return a;
}
#define LDSM4(r, addr) asm volatile( \
    "ldmatrix.sync.aligned.m8n8.x4.shared.b16 {%0,%1,%2,%3}, [%4];" \
    : "=r"((r)[0]), "=r"((r)[1]), "=r"((r)[2]), "=r"((r)[3]) : "r"(addr))
#define MMA(d, a, b0v, b1v) asm volatile( \
    "mma.sync.aligned.m16n8k16.row.col.f32.bf16.bf16.f32 " \
    "{%0,%1,%2,%3}, {%4,%5,%6,%7}, {%8,%9}, {%0,%1,%2,%3};" \
    : "+f"((d)[0]), "+f"((d)[1]), "+f"((d)[2]), "+f"((d)[3]) \
    : "r"((a)[0]), "r"((a)[1]), "r"((a)[2]), "r"((a)[3]), "r"(b0v), "r"(b1v))
__device__ __forceinline__ void cp_async16(uint32_t dst, const void* src) {
    asm volatile("cp.async.cg.shared.global [%0], [%1], 16;" :: "r"(dst), "l"(src));
}
#define CP_COMMIT() asm volatile("cp.async.commit_group;" ::: "memory")
__device__ __forceinline__ void st_release_u32(uint32_t* p, uint32_t v) {
    asm volatile("st.global.release.gpu.b32 [%0], %1;" :: "l"(p), "r"(v) : "memory");
}
__device__ __forceinline__ uint32_t ld_acquire_u32(const uint32_t* p) {
    uint32_t v;
    asm volatile("ld.global.acquire.gpu.b32 %0, [%1];" : "=r"(v) : "l"(p) : "memory");
    return v;
}

// ---------------------------------------------------------------------------
// W precompute (fp32 -> hi/lo bf16, permuted rows) + zero lookback flags.
// ---------------------------------------------------------------------------
__global__ void wsplit_kernel(const float* __restrict__ W_in, const float* __restrict__ W_f)
{
    int i = blockIdx.x * blockDim.x + threadIdx.x;
    if (i >= N_TOT * K_) return;
    g_flag[i] = 0u;
    int p = i >> 8, k = i & 255;
    int nb = p >> 8;
    int rem = p & 255;
    int branch = rem >> 7;
    int d = nb * 128 + (rem & 127);
    float v = branch ? W_f[d * K_ + k] : W_in[d * K_ + k];
    __nv_bfloat16 hi = __float2bfloat16_rn(v);
    ((__nv_bfloat16*)g_Whi4)[i] = hi;
    ((__nv_bfloat16*)g_Wlo4)[i] = __float2bfloat16_rn(v - __bfloat162float(hi));
}

// ---------------------------------------------------------------------------
// A precompute: fp32 -> hi/lo bf16 (row-major [m][k]). Pure streaming.
// ---------------------------------------------------------------------------
__global__ void asplit_kernel(const float4* __restrict__ A4)
{
    int i = blockIdx.x * blockDim.x + threadIdx.x;   // float4 id, 2,097,152 total
    float4 a = A4[i];
    __nv_bfloat16 h0 = __float2bfloat16_rn(a.x), h1 = __float2bfloat16_rn(a.y),
                  h2 = __float2bfloat16_rn(a.z), h3 = __float2bfloat16_rn(a.w);
    __nv_bfloat162 hp0 = {h0, h1}, hp1 = {h2, h3};
    __nv_bfloat162 lp0 = __floats2bfloat162_rn(a.x - __bfloat162float(h0),
                                               a.y - __bfloat162float(h1));
    __nv_bfloat162 lp1 = __floats2bfloat162_rn(a.z - __bfloat162float(h2),
                                               a.w - __bfloat162float(h3));
    ((uint2*)g_Ahi4)[i] = make_uint2(*(uint32_t*)&hp0, *(uint32_t*)&hp1);
    ((uint2*)g_Alo4)[i] = make_uint2(*(uint32_t*)&lp0, *(uint32_t*)&lp1);
}

// ---------------------------------------------------------------------------
// Fused: split-bf16 mma GEMM + activations + decoupled-lookback scan + output.
// grid = 1024 blocks (512 m-chunks x 2 n-halves), 512 threads.
// ---------------------------------------------------------------------------
__global__ __launch_bounds__(512, 1)
void fused_kernel(const float* __restrict__ b_in,
                  const float* __restrict__ b_f,
                  const float* __restrict__ mask,
                  float* __restrict__ out)
{
    extern __shared__ __align__(16) char smem[];
    const uint32_t sb = smem_u32(smem);
    const int tid = threadIdx.x;
    const int w   = tid >> 5, l = tid & 31;
    const int wm  = w >> 3;
    const int wn  = w & 7;
    const int bid = blockIdx.x;
    const int m0  = (bid >> 1) * 64;
    const int nb  = bid & 1;

    // W chunk issuer (no commit inside)
    auto issueW = [&](int kc, int buf) {
        uint32_t base = sb + (buf ? SM_W1 : SM_W0);
#pragma unroll
        for (int i = 0; i < 8; i++) {
            int v   = i * 512 + tid;
            int arr = v >> 11;
            int u   = v & 2047;
            int n   = u >> 3, uk = u & 7;
            uint32_t doff = n * 128 + ((uk ^ (n & 7)) << 4);
            const uint4* src = (arr ? g_Wlo4 : g_Whi4)
                             + ((size_t)(nb * 256 + n) * 32 + kc * 8 + uk);
            cp_async16(base + (arr ? SM_WLOFF : 0) + doff, src);
        }
    };

    // group 0: A tile (hi+lo, full K) + W chunk 0
#pragma unroll
    for (int i = 0; i < 8; i++) {
        int v   = i * 512 + tid;
        int arr = v >> 11;
        int u   = v & 2047;
        int row = u >> 5;
        int c8  = u & 31;                         // 16B chunk within row
        uint32_t dst = sb + (arr ? SM_ALO : SM_AHI)
                     + row * 512 + ((c8 ^ (row & 7)) << 4);
        const uint4* src = (arr ? g_Alo4 : g_Ahi4) + ((size_t)(m0 + row) * 32 + c8);
        cp_async16(dst, src);
    }
    issueW(0, 0);
    CP_COMMIT();
    // group 1: W chunk 1
    issueW(1, 1);
    CP_COMMIT();

    // bias / mask staging (regular smem stores, ordered by the barrier below)
    for (int i = tid; i < 256; i += 512) {
        int branch = i >> 7;
        int d = nb * 128 + (i & 127);
        *(float*)(smem + SM_BIAS + i * 4) = branch ? b_f[d] : b_in[d];
    }
    if (tid < 64) *(float*)(smem + SM_MK + tid * 4) = mask[m0 + tid] * 10000.0f;

    float acc[2][4][4];
#pragma unroll
    for (int a1 = 0; a1 < 2; a1++)
#pragma unroll
        for (int a2 = 0; a2 < 4; a2++)
#pragma unroll
            for (int a3 = 0; a3 < 4; a3++) acc[a1][a2][a3] = 0.0f;

    for (int kc = 0; kc < 4; kc++) {
        const int buf = kc & 1;
        if (kc < 3) asm volatile("cp.async.wait_group 1;" ::: "memory");
        else        asm volatile("cp.async.wait_group 0;" ::: "memory");
        __syncthreads();
        const uint32_t wbase = sb + (buf ? SM_W1 : SM_W0);

#pragma unroll
        for (int ks = 0; ks < 4; ks++) {
            const int g = l >> 3;

            uint32_t ah[2][4], al[2][4], bh[2][4], bl[2][4];
#pragma unroll
            for (int mt = 0; mt < 2; mt++) {
                int r = wm * 32 + mt * 16 + ((g & 1) << 3) + (l & 7);
                int c = kc * 64 + ks * 16 + ((g & 2) << 2);
                uint32_t off = r * 512 + ((((c >> 3) ^ (r & 7))) << 4);
                LDSM4(ah[mt], sb + SM_AHI + off);
                LDSM4(al[mt], sb + SM_ALO + off);
            }
#pragma unroll
            for (int ng = 0; ng < 2; ng++) {
                int n  = wn * 32 + ng * 16 + ((g & 2) << 2) + (l & 7);
                int kk = ks * 16 + ((g & 1) << 3);
                uint32_t woff = n * 128 + ((((kk >> 3) ^ (n & 7))) << 4);
                LDSM4(bh[ng], wbase + woff);
                LDSM4(bl[ng], wbase + SM_WLOFF + woff);
            }
            // term-major issue: 3 groups of 8 independent MMAs
#pragma unroll
            for (int mt = 0; mt < 2; mt++)
#pragma unroll
                for (int ng = 0; ng < 2; ng++) {
                    MMA(acc[mt][ng * 2 + 0], ah[mt], bh[ng][0], bh[ng][1]);
                    MMA(acc[mt][ng * 2 + 1], ah[mt], bh[ng][2], bh[ng][3]);
                }
#pragma unroll
            for (int mt = 0; mt < 2; mt++)
#pragma unroll
                for (int ng = 0; ng < 2; ng++) {
                    MMA(acc[mt][ng * 2 + 0], al[mt], bh[ng][0], bh[ng][1]);
                    MMA(acc[mt][ng * 2 + 1], al[mt], bh[ng][2], bh[ng][3]);
                }
#pragma unroll
            for (int mt = 0; mt < 2; mt++)
#pragma unroll
                for (int ng = 0; ng < 2; ng++) {
                    MMA(acc[mt][ng * 2 + 0], ah[mt], bl[ng][0], bl[ng][1]);
                    MMA(acc[mt][ng * 2 + 1], ah[mt], bl[ng][2], bl[ng][3]);
                }
        }
        __syncthreads();
        if (kc < 2) { issueW(kc + 2, buf); CP_COMMIT(); }
    }

    // -------- epilogue: activations -> smem staging --------
    float* xs = (float*)(smem + SM_XS);
    float* fs = (float*)(smem + SM_FS);
    const float* biasS = (const float*)(smem + SM_BIAS);
    const float* mkS   = (const float*)(smem + SM_MK);

#pragma unroll
    for (int mt = 0; mt < 2; mt++)
#pragma unroll
        for (int nt = 0; nt < 4; nt++) {
            int r0 = wm * 32 + mt * 16 + (l >> 2);
            int nl = wn * 32 + nt * 8 + 2 * (l & 3);
            bool isF = (nl >= 128);
            float* stg = isF ? fs : xs;
            int cc = nl & 127;
            float b0 = biasS[nl], b1 = biasS[nl + 1];
#pragma unroll
            for (int h = 0; h < 2; h++) {
                int r = r0 + h * 8;
                float z0 = acc[mt][nt][h * 2 + 0] + b0;
                float z1 = acc[mt][nt][h * 2 + 1] + b1;
                float v0, v1;
                if (isF) {
                    float mk = mkS[r];
                    z0 += mk; z1 += mk;
                    v0 = 1.0f / (1.0f + expf(-z0));
                    v1 = 1.0f / (1.0f + expf(-z1));
                } else {
                    v0 = tanhf(z0);
                    v1 = tanhf(z1);
                }
                stg[r * STG + cc]     = v0;
                stg[r * STG + cc + 1] = v1;
            }
        }
    __syncthreads();

    // -------- lookback scan: 128 threads, one per local channel --------
    if (tid < 128) {
        const int dl = tid;
        const int slot = bid * 128 + dl;

        float hl = 0.0f, Aa = 1.0f;
#pragma unroll 8
        for (int t = 0; t < LCH; t++) {
            float f = fs[t * STG + dl];
            float x = xs[t * STG + dl];
            float om = 1.0f - f;
            hl = fmaf(f, x, om * hl);
            Aa *= om;
        }

        const int c = (bid >> 1) & (NCH - 1);
        float h0 = 0.0f;
        if (c != 0) {
            g_SA [slot] = Aa;
            g_SHl[slot] = hl;
            st_release_u32(&g_flag[slot], 1u);
            float mult = 1.0f;
            int p = slot - 256;
            while (true) {
                uint32_t f;
                do { f = ld_acquire_u32(&g_flag[p]); } while (f == 0u);
                if (f == 2u) { h0 = fmaf(mult, g_SHI[p], h0); break; }
                h0 = fmaf(mult, g_SHl[p], h0);
                mult *= g_SA[p];
                p -= 256;
            }
        }
        g_SHI[slot] = fmaf(Aa, h0, hl);
        st_release_u32(&g_flag[slot], 2u);

        float h = h0;
        float* op = out + (size_t)m0 * D_ + nb * 128 + dl;
#pragma unroll 8
        for (int t = 0; t < LCH; t++) {
            float f = fs[t * STG + dl];
            float x = xs[t * STG + dl];
            h = fmaf(f, x - h, h);
            op[(size_t)t * D_] = h;
        }
    }
}

extern "C" void kernel_launch(void* const* d_in, const int* in_sizes, int n_in,
                              void* d_out, int out_size)
{
    const float* inputs = (const float*)d_in[0];
    const float* mask   = (const float*)d_in[1];
    const float* W_in   = (const float*)d_in[2];
    const float* b_in   = (const float*)d_in[3];
    const float* W_f    = (const float*)d_in[4];
    const float* b_f    = (const float*)d_in[5];
    float* out = (float*)d_out;

    cudaFuncSetAttribute(fused_kernel, cudaFuncAttributeMaxDynamicSharedMemorySize, SM_TOTAL);

    wsplit_kernel<<<(N_TOT * K_ + 255) / 256, 256>>>(W_in, W_f);
    asplit_kernel<<<(M_ * K_ / 4) / 256, 256>>>((const float4*)inputs);
    fused_kernel<<<NBLK, 512, SM_TOTAL>>>(b_in, b_f, mask, out);
}

// round 13
// speedup vs baseline: 1.1521x; 1.1521x over previous
#include <cuda_runtime.h>
#include <cuda_bf16.h>
#include <math.h>
#include <stdint.h>

// ---------------- problem constants ----------------
#define B_  8
#define T_  4096
#define D_  256
#define M_  (B_ * T_)      // 32768
#define K_  256
#define N_TOT 512

// ---------------- scan chunking ----------------
#define LCH 64
#define NCH (T_ / LCH)          // 64 chunks per batch
#define NBLK ((M_ / LCH) * 4)   // 2048 fused blocks (4 d-quadrants)

// ---------------- scratch (static device allocations) ----------------
__device__ uint4 g_Whi4[(N_TOT * K_) / 8];       // permuted rows (see prep)
__device__ uint4 g_Wlo4[(N_TOT * K_) / 8];
__device__ uint4 g_Ahi4[((size_t)M_ * K_) / 8];  // [m][k] bf16 hi
__device__ uint4 g_Alo4[((size_t)M_ * K_) / 8];  // [m][k] bf16 lo
// decoupled-lookback state: NBLK * 64 channels = 131072 slots
__device__ float    g_SA [NBLK * 64];
__device__ float    g_SHl[NBLK * 64];
__device__ float    g_SHI[NBLK * 64];
__device__ uint32_t g_flag[NBLK * 64];

// ---------------- smem layout ----------------
// stage: Ahi 8K | Alo 8K | Whi 16K | Wlo 16K = 48K; two stages = 96K
#define ST_ALO   8192
#define ST_WHI   16384
#define ST_WLO   32768
#define ST_SIZE  49152
#define SM_BIAS  98304      // 128 floats
#define SM_MK    98816      // 64 floats
#define SM_TOTAL 99072
// epilogue staging (reuses stage space after final sync)
#define SM_XS    0
#define SM_FS    20480
#define STG      68

// ---------------- asm helpers (base sm_103 features only) ----------------
__device__ __forceinline__ uint32_t smem_u32(const void* p) {
    uint32_t a;
    asm("{ .reg .u64 t; cvta.to.shared.u64 t, %1; cvt.u32.u64 %0, t; }" : "=r"(a) : "l"(p));
    return a;
}
#define LDSM4(r, addr) asm volatile( \
    "ldmatrix.sync.aligned.m8n8.x4.shared.b16 {%0,%1,%2,%3}, [%4];" \
    : "=r"((r)[0]), "=r"((r)[1]), "=r"((r)[2]), "=r"((r)[3]) : "r"(addr))
#define MMA(d, a, b0v, b1v) asm volatile( \
    "mma.sync.aligned.m16n8k16.row.col.f32.bf16.bf16.f32 " \
    "{%0,%1,%2,%3}, {%4,%5,%6,%7}, {%8,%9}, {%0,%1,%2,%3};" \
    : "+f"((d)[0]), "+f"((d)[1]), "+f"((d)[2]), "+f"((d)[3]) \
    : "r"((a)[0]), "r"((a)[1]), "r"((a)[2]), "r"((a)[3]), "r"(b0v), "r"(b1v))
__device__ __forceinline__ void cp_async16(uint32_t dst, const void* src) {
    asm volatile("cp.async.cg.shared.global [%0], [%1], 16;" :: "r"(dst), "l"(src));
}
#define CP_COMMIT() asm volatile("cp.async.commit_group;" ::: "memory")
__device__ __forceinline__ void st_release_u32(uint32_t* p, uint32_t v) {
    asm volatile("st.global.release.gpu.b32 [%0], %1;" :: "l"(p), "r"(v) : "memory");
}
__device__ __forceinline__ uint32_t ld_acquire_u32(const uint32_t* p) {
    uint32_t v;
    asm volatile("ld.global.acquire.gpu.b32 %0, [%1];" : "=r"(v) : "l"(p) : "memory");
    return v;
}

// ---------------------------------------------------------------------------
// prep: A fp32 -> hi/lo bf16 (all threads); W split + flag zero (first slice).
// W permuted rows: p = qb*128 + branch*64 + (d & 63), qb = d >> 6.
// ---------------------------------------------------------------------------
__global__ void prep_kernel(const float4* __restrict__ A4,
                            const float* __restrict__ W_in,
                            const float* __restrict__ W_f)
{
    int i = blockIdx.x * blockDim.x + threadIdx.x;   // 0 .. 2,097,151
    float4 a = A4[i];
    __nv_bfloat16 h0 = __float2bfloat16_rn(a.x), h1 = __float2bfloat16_rn(a.y),
                  h2 = __float2bfloat16_rn(a.z), h3 = __float2bfloat16_rn(a.w);
    __nv_bfloat162 hp0 = {h0, h1}, hp1 = {h2, h3};
    __nv_bfloat162 lp0 = __floats2bfloat162_rn(a.x - __bfloat162float(h0),
                                               a.y - __bfloat162float(h1));
    __nv_bfloat162 lp1 = __floats2bfloat162_rn(a.z - __bfloat162float(h2),
                                               a.w - __bfloat162float(h3));
    ((uint2*)g_Ahi4)[i] = make_uint2(*(uint32_t*)&hp0, *(uint32_t*)&hp1);
    ((uint2*)g_Alo4)[i] = make_uint2(*(uint32_t*)&lp0, *(uint32_t*)&lp1);

    if (i < NBLK * 64) {             // == N_TOT*K_ == 131072
        g_flag[i] = 0u;
        int p = i >> 8, k = i & 255;
        int qb = p >> 7;
        int rem = p & 127;
        int branch = rem >> 6;
        int d = qb * 64 + (rem & 63);
        float v = branch ? W_f[d * K_ + k] : W_in[d * K_ + k];
        __nv_bfloat16 hi = __float2bfloat16_rn(v);
        ((__nv_bfloat16*)g_Whi4)[i] = hi;
        ((__nv_bfloat16*)g_Wlo4)[i] = __float2bfloat16_rn(v - __bfloat162float(hi));
    }
}

// ---------------------------------------------------------------------------
// Fused: split-bf16 mma GEMM + activations + decoupled-lookback scan + output.
// grid = 2048 blocks (512 m-chunks x 4 d-quadrants), 512 threads, 2 CTA/SM.
// Block tile: 64 m x 128 n  (n_local 0..63 = X cols, 64..127 = F cols, same d).
// 16 warps, each 16 m x 32 n.
// ---------------------------------------------------------------------------
__global__ __launch_bounds__(512, 2)
void fused_kernel(const float* __restrict__ b_in,
                  const float* __restrict__ b_f,
                  const float* __restrict__ mask,
                  float* __restrict__ out)
{
    extern __shared__ __align__(16) char smem[];
    const uint32_t sb = smem_u32(smem);
    const int tid = threadIdx.x;
    const int w   = tid >> 5, l = tid & 31;
    const int wm  = w >> 2;           // 0..3, 16-row strip
    const int wn  = w & 3;            // 0..3, 32-col strip
    const int bid = blockIdx.x;
    const int m0  = (bid >> 2) * 64;
    const int qb  = bid & 3;

    // issue one stage = A chunk (hi+lo) + W chunk (hi+lo) for k-chunk kc
    auto issueStage = [&](int kc, int buf) {
        const uint32_t base = sb + (buf ? ST_SIZE : 0);
        // A: 64 rows x 8 u4 x 2 arrays = 1024 -> 2 per thread
#pragma unroll
        for (int it = 0; it < 2; it++) {
            int v   = it * 512 + tid;
            int arr = v >> 9;
            int u   = v & 511;
            int row = u >> 3, c8 = u & 7;
            uint32_t dst = base + (arr ? ST_ALO : 0)
                         + row * 128 + ((c8 ^ (row & 7)) << 4);
            const uint4* src = (arr ? g_Alo4 : g_Ahi4)
                             + ((size_t)(m0 + row) * 32 + kc * 8 + c8);
            cp_async16(dst, src);
        }
        // W: 128 rows x 8 u4 x 2 arrays = 2048 -> 4 per thread
#pragma unroll
        for (int it = 0; it < 4; it++) {
            int v   = it * 512 + tid;
            int arr = v >> 10;
            int u   = v & 1023;
            int n   = u >> 3, k8 = u & 7;
            uint32_t dst = base + (arr ? ST_WLO : ST_WHI)
                         + n * 128 + ((k8 ^ (n & 7)) << 4);
            const uint4* src = (arr ? g_Wlo4 : g_Whi4)
                             + ((size_t)(qb * 128 + n) * 32 + kc * 8 + k8);
            cp_async16(dst, src);
        }
        CP_COMMIT();
    };

    issueStage(0, 0);
    issueStage(1, 1);

    // bias / mask staging
    if (tid < 128) {
        int branch = tid >> 6;
        int d = qb * 64 + (tid & 63);
        *(float*)(smem + SM_BIAS + tid * 4) = branch ? b_f[d] : b_in[d];
    }
    if (tid < 64) *(float*)(smem + SM_MK + tid * 4) = mask[m0 + tid] * 10000.0f;

    float acc[4][4];
#pragma unroll
    for (int a2 = 0; a2 < 4; a2++)
#pragma unroll
        for (int a3 = 0; a3 < 4; a3++) acc[a2][a3] = 0.0f;

    const int g = l >> 3;

    for (int kc = 0; kc < 4; kc++) {
        const int buf = kc & 1;
        if (kc < 3) asm volatile("cp.async.wait_group 1;" ::: "memory");
        else        asm volatile("cp.async.wait_group 0;" ::: "memory");
        __syncthreads();
        const uint32_t base = sb + (buf ? ST_SIZE : 0);

#pragma unroll
        for (int ks = 0; ks < 4; ks++) {
            // A fragments: 16 m x 16 k
            uint32_t ah[4], al[4];
            {
                int r = wm * 16 + ((g & 1) << 3) + (l & 7);
                int c = ks * 16 + ((g & 2) << 2);
                uint32_t off = r * 128 + ((((c >> 3) ^ (r & 7))) << 4);
                LDSM4(ah, base + off);
                LDSM4(al, base + ST_ALO + off);
            }
            // W fragments: two 16-n groups
            uint32_t bh[2][4], bl[2][4];
#pragma unroll
            for (int ng = 0; ng < 2; ng++) {
                int n  = wn * 32 + ng * 16 + ((g & 2) << 2) + (l & 7);
                int kk = ks * 16 + ((g & 1) << 3);
                uint32_t woff = n * 128 + ((((kk >> 3) ^ (n & 7))) << 4);
                LDSM4(bh[ng], base + ST_WHI + woff);
                LDSM4(bl[ng], base + ST_WLO + woff);
            }
            // term-major: 3 groups of 4 independent MMAs
#pragma unroll
            for (int ng = 0; ng < 2; ng++) {
                MMA(acc[ng * 2 + 0], ah, bh[ng][0], bh[ng][1]);
                MMA(acc[ng * 2 + 1], ah, bh[ng][2], bh[ng][3]);
            }
#pragma unroll
            for (int ng = 0; ng < 2; ng++) {
                MMA(acc[ng * 2 + 0], al, bh[ng][0], bh[ng][1]);
                MMA(acc[ng * 2 + 1], al, bh[ng][2], bh[ng][3]);
            }
#pragma unroll
            for (int ng = 0; ng < 2; ng++) {
                MMA(acc[ng * 2 + 0], ah, bl[ng][0], bl[ng][1]);
                MMA(acc[ng * 2 + 1], ah, bl[ng][2], bl[ng][3]);
            }
        }
        __syncthreads();
        if (kc < 2) issueStage(kc + 2, buf);
    }

    // -------- epilogue: activations -> smem staging --------
    float* xs = (float*)(smem + SM_XS);
    float* fs = (float*)(smem + SM_FS);
    const float* biasS = (const float*)(smem + SM_BIAS);
    const float* mkS   = (const float*)(smem + SM_MK);

#pragma unroll
    for (int nt = 0; nt < 4; nt++) {
        int r0 = wm * 16 + (l >> 2);
        int nl = wn * 32 + nt * 8 + 2 * (l & 3);
        bool isF = (nl >= 64);
        float* stg = isF ? fs : xs;
        int cc = nl & 63;
        float b0 = biasS[nl], b1 = biasS[nl + 1];
#pragma unroll
        for (int h = 0; h < 2; h++) {
            int r = r0 + h * 8;
            float z0 = acc[nt][h * 2 + 0] + b0;
            float z1 = acc[nt][h * 2 + 1] + b1;
            float v0, v1;
            if (isF) {
                float mk = mkS[r];
                z0 += mk; z1 += mk;
                v0 = 1.0f / (1.0f + expf(-z0));
                v1 = 1.0f / (1.0f + expf(-z1));
            } else {
                v0 = tanhf(z0);
                v1 = tanhf(z1);
            }
            stg[r * STG + cc]     = v0;
            stg[r * STG + cc + 1] = v1;
        }
    }
    __syncthreads();

    // -------- lookback scan: 64 threads, one per local channel --------
    if (tid < 64) {
        const int dl = tid;
        const int slot = bid * 64 + dl;

        float hl = 0.0f, Aa = 1.0f;
#pragma unroll 8
        for (int t = 0; t < LCH; t++) {
            float f = fs[t * STG + dl];
            float x = xs[t * STG + dl];
            float om = 1.0f - f;
            hl = fmaf(f, x, om * hl);
            Aa *= om;
        }

        const int c = (bid >> 2) & (NCH - 1);   // chunk index within batch
        float h0 = 0.0f;
        if (c != 0) {
            g_SA [slot] = Aa;
            g_SHl[slot] = hl;
            st_release_u32(&g_flag[slot], 1u);
            float mult = 1.0f;
            int p = slot - 256;                 // (bid-4)*64 + dl
            while (true) {
                uint32_t f;
                do { f = ld_acquire_u32(&g_flag[p]); } while (f == 0u);
                if (f == 2u) { h0 = fmaf(mult, g_SHI[p], h0); break; }
                h0 = fmaf(mult, g_SHl[p], h0);
                mult *= g_SA[p];
                p -= 256;
            }
        }
        g_SHI[slot] = fmaf(Aa, h0, hl);
        st_release_u32(&g_flag[slot], 2u);

        float h = h0;
        float* op = out + (size_t)m0 * D_ + qb * 64 + dl;
#pragma unroll 8
        for (int t = 0; t < LCH; t++) {
            float f = fs[t * STG + dl];
            float x = xs[t * STG + dl];
            h = fmaf(f, x - h, h);
            op[(size_t)t * D_] = h;
        }
    }
}

extern "C" void kernel_launch(void* const* d_in, const int* in_sizes, int n_in,
                              void* d_out, int out_size)
{
    const float* inputs = (const float*)d_in[0];
    const float* mask   = (const float*)d_in[1];
    const float* W_in   = (const float*)d_in[2];
    const float* b_in   = (const float*)d_in[3];
    const float* W_f    = (const float*)d_in[4];
    const float* b_f    = (const float*)d_in[5];
    float* out = (float*)d_out;

    cudaFuncSetAttribute(fused_kernel, cudaFuncAttributeMaxDynamicSharedMemorySize, SM_TOTAL);

    prep_kernel<<<(M_ * K_ / 4) / 256, 256>>>((const float4*)inputs, W_in, W_f);
    fused_kernel<<<NBLK, 512, SM_TOTAL>>>(b_in, b_f, mask, out);
}